// round 15
// baseline (speedup 1.0000x reference)
#include <cuda_runtime.h>
#include <cuda_fp16.h>
#include <mma.h>
#include <math.h>

using namespace nvcuda;

#define N_NODES 50000
#define NPAD 50048          // 782 * 64
#define N_EDGES 400000
#define N_GRAPHS 512
#define NF 64
#define EF 32
#define AIF 92
#define AIFP 96
#define FCF 128
#define NLAYERS 3
#define TBINS 16384
#define TROWS 16385
#define BN_EPS 1e-5f

// ---------------- static scratch ----------------
__device__ __align__(16) float   d_h[NPAD * NF];
__device__ __align__(16) __half  d_hh[NPAD * NF];
__device__ __align__(16) float   d_agg[NPAD * NF];
__device__ __align__(16) __half2 d_ABp[NPAD * 128];            // packed (i,u): [0..63]=A, [64..127]=B
__device__ __align__(16) __half2 d_tab[NLAYERS * TROWS * 64];  // RBF@W table (nearest bin)
__device__ __align__(16) __half  d_wbigh[NLAYERS * 64 * 256];
__device__ __align__(16) __half  d_atomh[NPAD * AIFP];
__device__ __align__(16) __half  d_wembh[AIFP * NF];
__device__ int   d_counts[N_NODES];
__device__ int   d_rowstart[N_NODES + 1];
__device__ int   d_cursor[N_NODES];
__device__ int   d_bsum[128];
__device__ int   d_boff[128];
__device__ int   d_csr_eid[N_EDGES];
__device__ __align__(8) int2 d_e2[N_EDGES];    // (src, tbin), dst implicit in CSR position
__device__ float d_estat[NLAYERS * 256];
__device__ float d_nstat[NLAYERS * 128];

// ---------------- fast math ----------------
__device__ __forceinline__ float fsig(float x) {
    float t, hx = 0.5f * x;
    asm("tanh.approx.f32 %0, %1;" : "=f"(t) : "f"(hx));
    return fmaf(0.5f, t, 0.5f);
}
__device__ __forceinline__ float fsp(float x) {
    return fmaxf(x, 0.f) + __logf(1.f + __expf(-fabsf(x)));
}

// ---------------- prep: pack fp16 weights (interleaved) + embed weights, zero stat slabs ----
__global__ void k_wbig(const float* __restrict__ Wi, const float* __restrict__ Wu,
                       const float* __restrict__ Wemb) {
    int tid = threadIdx.x;
    int idx = blockIdx.x * blockDim.x + tid;
    if (blockIdx.x == 0) {
        if (tid < NLAYERS * 256) d_estat[tid] = 0.f;
    } else if (blockIdx.x == 1) {
        if (tid < NLAYERS * 128) d_nstat[tid] = 0.f;
    }
    for (int i = idx; i < N_NODES; i += gridDim.x * blockDim.x) d_counts[i] = 0;
    if (idx < NLAYERS * 64 * 256) {
        int l = idx / 16384;
        int r = idx - l * 16384;
        int k = r >> 8;
        int c = r & 255;
        float v;
        if (c < 128) {
            int f = c >> 1;
            int base = (l * 160 + k) * 64 + f;
            v = (c & 1) ? Wu[base] : Wi[base];
        } else {
            int f = (c - 128) >> 1;
            int base = (l * 160 + 64 + k) * 64 + f;
            v = (c & 1) ? Wu[base] : Wi[base];
        }
        d_wbigh[idx] = __float2half(v);
    } else {
        int w = idx - NLAYERS * 64 * 256;
        if (w < AIFP * NF) {
            int k = w >> 6, c = w & 63;
            d_wembh[w] = __float2half(k < AIF ? Wemb[k * 64 + c] : 0.f);
        }
    }
}

// ---------------- table build ----------------
#define TCH 64
#define TBLK 257
__global__ __launch_bounds__(256) void k_table(const float* __restrict__ Wi,
                                               const float* __restrict__ Wu) {
    int b = blockIdx.x;
    int l = b / TBLK;
    int t0 = (b - l * TBLK) * TCH;
    int tid = threadIdx.x;
    __shared__ float ws[2][32 * 64];
    __shared__ float es[TCH * 32];
    for (int idx = tid; idx < 32 * 64; idx += 256) {
        int k = idx >> 6, f = idx & 63;
        ws[0][idx] = Wi[(l * 160 + 128 + k) * 64 + f];
        ws[1][idx] = Wu[(l * 160 + 128 + k) * 64 + f];
    }
    for (int idx = tid; idx < TCH * 32; idx += 256) {
        int tl = idx >> 5, k = idx & 31;
        int t = t0 + tl;
        float d = (float)t * (8.0f / (float)TBINS);
        float ck = (float)k * (8.0f / 31.0f);
        float df = d - ck;
        es[idx] = (t < TROWS) ? __expf(-3.875f * df * df) : 0.f;
    }
    __syncthreads();
    for (int o = tid; o < TCH * 64; o += 256) {
        int tl = o >> 6, f = o & 63;
        int t = t0 + tl;
        if (t >= TROWS) continue;
        float ai = 0.f, au = 0.f;
#pragma unroll
        for (int k = 0; k < 32; k++) {
            float e = es[tl * 32 + k];
            ai = fmaf(e, ws[0][k * 64 + f], ai);
            au = fmaf(e, ws[1][k * 64 + f], au);
        }
        d_tab[(l * TROWS + t) * 64 + f] = __floats2half2_rn(ai, au);
    }
}

// ---------------- fp16 conversion of atom features ----------------
__global__ void k_convatom(const float* __restrict__ atom) {
    int idx = blockIdx.x * blockDim.x + threadIdx.x;
    if (idx >= NPAD * 24) return;
    int row = idx / 24, c4 = idx - row * 24;
    float4 v = make_float4(0.f, 0.f, 0.f, 0.f);
    if (row < N_NODES && c4 < 23) v = *(const float4*)&atom[row * AIF + c4 * 4];
    __half2* o = (__half2*)&d_atomh[row * AIFP + c4 * 4];
    o[0] = __floats2half2_rn(v.x, v.y);
    o[1] = __floats2half2_rn(v.z, v.w);
}

// ---------------- CSR build ----------------
__global__ void k_count(const int* __restrict__ dst) {
    int e = blockIdx.x * blockDim.x + threadIdx.x;
    if (e < N_EDGES) atomicAdd(&d_counts[dst[e]], 1);
}

__global__ void k_scan1() {
    int b = blockIdx.x, tid = threadIdx.x;
    int i = b * 512 + tid;
    int v = (i < N_NODES) ? d_counts[i] : 0;
    __shared__ int s[512];
    s[tid] = v;
    __syncthreads();
    for (int o = 1; o < 512; o <<= 1) {
        int t = (tid >= o) ? s[tid - o] : 0;
        __syncthreads();
        s[tid] += t;
        __syncthreads();
    }
    if (i < N_NODES) d_rowstart[i] = s[tid] - v;
    if (tid == 511) d_bsum[b] = s[511];
}

__global__ void k_scan2(int nblk) {
    int tid = threadIdx.x;
    int v = (tid < nblk) ? d_bsum[tid] : 0;
    __shared__ int s[128];
    s[tid] = v;
    __syncthreads();
    for (int o = 1; o < 128; o <<= 1) {
        int t = (tid >= o) ? s[tid - o] : 0;
        __syncthreads();
        s[tid] += t;
        __syncthreads();
    }
    d_boff[tid] = s[tid] - v;
}

__global__ void k_scan3() {
    int i = blockIdx.x * blockDim.x + threadIdx.x;
    if (i >= N_NODES) return;
    int rs = d_rowstart[i] + d_boff[i >> 9];
    d_rowstart[i] = rs;
    d_cursor[i] = rs;
    if (i == 0) d_rowstart[N_NODES] = N_EDGES;
}

__global__ void k_fill(const int* __restrict__ dst) {
    int e = blockIdx.x * blockDim.x + threadIdx.x;
    if (e >= N_EDGES) return;
    int pos = atomicAdd(&d_cursor[dst[e]], 1);
    d_csr_eid[pos] = e;
}

__global__ void k_sortg(const int* __restrict__ src, const float* __restrict__ bond) {
    int n = blockIdx.x * blockDim.x + threadIdx.x;
    if (n >= N_NODES) return;
    int s = d_rowstart[n], e = d_rowstart[n + 1];
    for (int i = s + 1; i < e; i++) {
        int v = d_csr_eid[i];
        int j = i - 1;
        while (j >= s && d_csr_eid[j] > v) {
            d_csr_eid[j + 1] = d_csr_eid[j];
            j--;
        }
        d_csr_eid[j + 1] = v;
    }
    for (int i = s; i < e; i++) {
        int eid = d_csr_eid[i];
        int ss = src[eid];
        int t = __float2int_rn(bond[eid] * ((float)TBINS / 8.0f));
        d_e2[i] = make_int2(ss, t);
    }
}

// ---------------- embed GEMM via HMMA ----------------
__global__ __launch_bounds__(256) void k_gemm_embh(const float* __restrict__ bias) {
    int m0 = blockIdx.x * 128;
    int wid = threadIdx.x >> 5;
    int lane = threadIdx.x & 31;
    int mw = wid & 3;
    int nw = wid >> 2;

    wmma::fragment<wmma::accumulator, 16, 16, 16, float> acc[2][2];
#pragma unroll
    for (int mi = 0; mi < 2; mi++)
#pragma unroll
        for (int nj = 0; nj < 2; nj++) wmma::fill_fragment(acc[mi][nj], 0.f);

#pragma unroll
    for (int kk = 0; kk < 6; kk++) {
        wmma::fragment<wmma::matrix_a, 16, 16, 16, __half, wmma::row_major> af[2];
        wmma::fragment<wmma::matrix_b, 16, 16, 16, __half, wmma::row_major> bf[2];
#pragma unroll
        for (int mi = 0; mi < 2; mi++)
            wmma::load_matrix_sync(af[mi], d_atomh + (m0 + mw * 32 + mi * 16) * AIFP + kk * 16, AIFP);
#pragma unroll
        for (int nj = 0; nj < 2; nj++)
            wmma::load_matrix_sync(bf[nj], d_wembh + (kk * 16) * 64 + nw * 32 + nj * 16, 64);
#pragma unroll
        for (int mi = 0; mi < 2; mi++)
#pragma unroll
            for (int nj = 0; nj < 2; nj++)
                wmma::mma_sync(acc[mi][nj], af[mi], bf[nj], acc[mi][nj]);
    }

    __shared__ float patch[8][256];
    float* p = patch[wid];
#pragma unroll
    for (int mi = 0; mi < 2; mi++)
#pragma unroll
        for (int nj = 0; nj < 2; nj++) {
            wmma::store_matrix_sync(p, acc[mi][nj], 16, wmma::mem_row_major);
            __syncwarp();
            int row0 = m0 + mw * 32 + mi * 16;
            int col0 = nw * 32 + nj * 16;
#pragma unroll
            for (int j = 0; j < 8; j++) {
                int q = lane + 32 * j;
                int r = q >> 4, c = q & 15;
                float v = p[r * 16 + c] + bias[col0 + c];
                int o = (row0 + r) * 64 + col0 + c;
                d_h[o] = v;
                d_hh[o] = __float2half(v);
            }
            __syncwarp();
        }
}

// ---------------- layer GEMM via HMMA ----------------
__global__ __launch_bounds__(256) void k_gemmAB(int layer) {
    const __half* A = d_hh;
    const __half* B = d_wbigh + layer * 64 * 256;
    int m0 = blockIdx.x * 64;
    int wid = threadIdx.x >> 5;
    int lane = threadIdx.x & 31;
    int mw = wid & 1;
    int nw = wid >> 1;

    wmma::fragment<wmma::accumulator, 16, 16, 16, float> acc[2][4];
#pragma unroll
    for (int mi = 0; mi < 2; mi++)
#pragma unroll
        for (int nj = 0; nj < 4; nj++) wmma::fill_fragment(acc[mi][nj], 0.f);

#pragma unroll
    for (int kk = 0; kk < 4; kk++) {
        wmma::fragment<wmma::matrix_a, 16, 16, 16, __half, wmma::row_major> af[2];
        wmma::fragment<wmma::matrix_b, 16, 16, 16, __half, wmma::row_major> bf[4];
#pragma unroll
        for (int mi = 0; mi < 2; mi++)
            wmma::load_matrix_sync(af[mi], A + (m0 + mw * 32 + mi * 16) * 64 + kk * 16, 64);
#pragma unroll
        for (int nj = 0; nj < 4; nj++)
            wmma::load_matrix_sync(bf[nj], B + (kk * 16) * 256 + nw * 64 + nj * 16, 256);
#pragma unroll
        for (int mi = 0; mi < 2; mi++)
#pragma unroll
            for (int nj = 0; nj < 4; nj++)
                wmma::mma_sync(acc[mi][nj], af[mi], bf[nj], acc[mi][nj]);
    }

    __shared__ float patch[8][256];
    float* p = patch[wid];
#pragma unroll
    for (int mi = 0; mi < 2; mi++)
#pragma unroll
        for (int nj = 0; nj < 4; nj++) {
            wmma::store_matrix_sync(p, acc[mi][nj], 16, wmma::mem_row_major);
            __syncwarp();
            int row0 = m0 + mw * 32 + mi * 16;
            int pairbase = nw * 32 + nj * 8;
#pragma unroll
            for (int j = 0; j < 4; j++) {
                int q = lane * 4 + j;
                int r = q >> 3, pp = q & 7;
                d_ABp[(row0 + r) * 128 + pairbase + pp] =
                    __floats2half2_rn(p[r * 16 + 2 * pp], p[r * 16 + 2 * pp + 1]);
            }
            __syncwarp();
        }
}

// ---------------- stats: node-centric, uint2 row fragments (feats 2l, 2l+1), 4-edge batches ----
__global__ __launch_bounds__(256) void k_stats(int layer) {
    int tid = threadIdx.x;
    int wid = tid >> 5, lane = tid & 31;
    int f0 = 2 * lane;                 // lane covers features f0, f0+1
    const __half2* Tb = d_tab + layer * TROWS * 64;
    float s1i0 = 0.f, s2i0 = 0.f, s1u0 = 0.f, s2u0 = 0.f;
    float s1i1 = 0.f, s2i1 = 0.f, s1u1 = 0.f, s2u1 = 0.f;
    for (int n = blockIdx.x * 8 + wid; n < N_NODES; n += gridDim.x * 8) {
        int a0 = d_rowstart[n], a1 = d_rowstart[n + 1];
        uint2 bb = *(const uint2*)&d_ABp[n * 128 + 64 + f0];
        float2 b0 = __half22float2(*reinterpret_cast<__half2*>(&bb.x));
        float2 b1 = __half22float2(*reinterpret_cast<__half2*>(&bb.y));
        int i = a0;
        for (; i + 4 <= a1; i += 4) {
            int2 e[4];
            uint2 av[4], uv[4];
#pragma unroll
            for (int j = 0; j < 4; j++) e[j] = d_e2[i + j];
#pragma unroll
            for (int j = 0; j < 4; j++) {
                av[j] = *(const uint2*)&d_ABp[e[j].x * 128 + f0];
                uv[j] = *(const uint2*)&Tb[e[j].y * 64 + f0];
            }
#pragma unroll
            for (int j = 0; j < 4; j++) {
                float2 a0v = __half22float2(*reinterpret_cast<__half2*>(&av[j].x));
                float2 a1v = __half22float2(*reinterpret_cast<__half2*>(&av[j].y));
                float2 u0 = __half22float2(*reinterpret_cast<__half2*>(&uv[j].x));
                float2 u1 = __half22float2(*reinterpret_cast<__half2*>(&uv[j].y));
                float pi0 = a0v.x + b0.x + u0.x;
                float pu0 = a0v.y + b0.y + u0.y;
                float pi1 = a1v.x + b1.x + u1.x;
                float pu1 = a1v.y + b1.y + u1.y;
                s1i0 += pi0; s2i0 = fmaf(pi0, pi0, s2i0);
                s1u0 += pu0; s2u0 = fmaf(pu0, pu0, s2u0);
                s1i1 += pi1; s2i1 = fmaf(pi1, pi1, s2i1);
                s1u1 += pu1; s2u1 = fmaf(pu1, pu1, s2u1);
            }
        }
        for (; i < a1; i++) {
            int2 e = d_e2[i];
            uint2 a = *(const uint2*)&d_ABp[e.x * 128 + f0];
            uint2 u = *(const uint2*)&Tb[e.y * 64 + f0];
            float2 a0v = __half22float2(*reinterpret_cast<__half2*>(&a.x));
            float2 a1v = __half22float2(*reinterpret_cast<__half2*>(&a.y));
            float2 u0 = __half22float2(*reinterpret_cast<__half2*>(&u.x));
            float2 u1 = __half22float2(*reinterpret_cast<__half2*>(&u.y));
            float pi0 = a0v.x + b0.x + u0.x;
            float pu0 = a0v.y + b0.y + u0.y;
            float pi1 = a1v.x + b1.x + u1.x;
            float pu1 = a1v.y + b1.y + u1.y;
            s1i0 += pi0; s2i0 = fmaf(pi0, pi0, s2i0);
            s1u0 += pu0; s2u0 = fmaf(pu0, pu0, s2u0);
            s1i1 += pi1; s2i1 = fmaf(pi1, pi1, s2i1);
            s1u1 += pu1; s2u1 = fmaf(pu1, pu1, s2u1);
        }
    }
    float* es = d_estat + layer * 256;
    __shared__ float red[256];
    // reducer thread t (<32) owns features 2t, 2t+1
#define RED8(val, base, odd)                                                       \
    red[tid] = (val); __syncthreads();                                             \
    if (tid < 32) { float a = 0.f;                                                 \
        for (int w = 0; w < 8; w++) a += red[w * 32 + tid];                        \
        atomicAdd(&es[(base) + 2 * tid + (odd)], a); }                             \
    __syncthreads();
    RED8(s1i0, 0, 0)
    RED8(s1i1, 0, 1)
    RED8(s2i0, 64, 0)
    RED8(s2i1, 64, 1)
    RED8(s1u0, 128, 0)
    RED8(s1u1, 128, 1)
    RED8(s2u0, 192, 0)
    RED8(s2u1, 192, 1)
#undef RED8
}

// ---------------- apply: warp-per-node, uint2 row fragments, 4-edge batches, fused edge-BN ----
__global__ __launch_bounds__(256) void k_apply(const float* __restrict__ gi,
                                               const float* __restrict__ bti,
                                               const float* __restrict__ gu,
                                               const float* __restrict__ btu,
                                               int layer) {
    __shared__ float sci[64], shi[64], scu[64], shu[64];
    int tid = threadIdx.x;
    if (tid < 128) {
        const float* es = d_estat + layer * 256;
        int c = tid;
        if (c < 64) {
            float mean = es[c] * (1.f / N_EDGES);
            float var = es[64 + c] * (1.f / N_EDGES) - mean * mean;
            float s = gi[layer * 64 + c] * rsqrtf(var + BN_EPS);
            sci[c] = s; shi[c] = bti[layer * 64 + c] - mean * s;
        } else {
            int f = c - 64;
            float mean = es[128 + f] * (1.f / N_EDGES);
            float var = es[192 + f] * (1.f / N_EDGES) - mean * mean;
            float s = gu[layer * 64 + f] * rsqrtf(var + BN_EPS);
            scu[f] = s; shu[f] = btu[layer * 64 + f] - mean * s;
        }
    }
    __syncthreads();
    int wid = tid >> 5, lane = tid & 31;
    int f0 = 2 * lane;
    float ci0 = sci[f0], hi0 = shi[f0], cu0 = scu[f0], hu0 = shu[f0];
    float ci1 = sci[f0 + 1], hi1 = shi[f0 + 1], cu1 = scu[f0 + 1], hu1 = shu[f0 + 1];
    const __half2* Tb = d_tab + layer * TROWS * 64;
    float s1_0 = 0.f, s2_0 = 0.f, s1_1 = 0.f, s2_1 = 0.f;
    for (int n = blockIdx.x * 8 + wid; n < N_NODES; n += gridDim.x * 8) {
        int a0 = d_rowstart[n], a1 = d_rowstart[n + 1];
        uint2 bb = *(const uint2*)&d_ABp[n * 128 + 64 + f0];
        float2 b0 = __half22float2(*reinterpret_cast<__half2*>(&bb.x));
        float2 b1 = __half22float2(*reinterpret_cast<__half2*>(&bb.y));
        float acc0 = 0.f, acc1 = 0.f;
        int i = a0;
        for (; i + 4 <= a1; i += 4) {
            int2 e[4];
            uint2 av[4], uv[4];
#pragma unroll
            for (int j = 0; j < 4; j++) e[j] = d_e2[i + j];
#pragma unroll
            for (int j = 0; j < 4; j++) {
                av[j] = *(const uint2*)&d_ABp[e[j].x * 128 + f0];
                uv[j] = *(const uint2*)&Tb[e[j].y * 64 + f0];
            }
#pragma unroll
            for (int j = 0; j < 4; j++) {
                float2 a0v = __half22float2(*reinterpret_cast<__half2*>(&av[j].x));
                float2 a1v = __half22float2(*reinterpret_cast<__half2*>(&av[j].y));
                float2 u0 = __half22float2(*reinterpret_cast<__half2*>(&uv[j].x));
                float2 u1 = __half22float2(*reinterpret_cast<__half2*>(&uv[j].y));
                acc0 = fmaf(fsig(fmaf(a0v.x + b0.x + u0.x, ci0, hi0)),
                            fsp(fmaf(a0v.y + b0.y + u0.y, cu0, hu0)), acc0);
                acc1 = fmaf(fsig(fmaf(a1v.x + b1.x + u1.x, ci1, hi1)),
                            fsp(fmaf(a1v.y + b1.y + u1.y, cu1, hu1)), acc1);
            }
        }
        for (; i < a1; i++) {
            int2 e = d_e2[i];
            uint2 a = *(const uint2*)&d_ABp[e.x * 128 + f0];
            uint2 u = *(const uint2*)&Tb[e.y * 64 + f0];
            float2 a0v = __half22float2(*reinterpret_cast<__half2*>(&a.x));
            float2 a1v = __half22float2(*reinterpret_cast<__half2*>(&a.y));
            float2 u0 = __half22float2(*reinterpret_cast<__half2*>(&u.x));
            float2 u1 = __half22float2(*reinterpret_cast<__half2*>(&u.y));
            acc0 = fmaf(fsig(fmaf(a0v.x + b0.x + u0.x, ci0, hi0)),
                        fsp(fmaf(a0v.y + b0.y + u0.y, cu0, hu0)), acc0);
            acc1 = fmaf(fsig(fmaf(a1v.x + b1.x + u1.x, ci1, hi1)),
                        fsp(fmaf(a1v.y + b1.y + u1.y, cu1, hu1)), acc1);
        }
        *(float2*)&d_agg[n * 64 + f0] = make_float2(acc0, acc1);
        s1_0 += acc0; s2_0 = fmaf(acc0, acc0, s2_0);
        s1_1 += acc1; s2_1 = fmaf(acc1, acc1, s2_1);
    }
    float* ns = d_nstat + layer * 128;
    __shared__ float red[256];
#define RED4(val, base, odd)                                                       \
    red[tid] = (val); __syncthreads();                                             \
    if (tid < 32) { float a = 0.f;                                                 \
        for (int w = 0; w < 8; w++) a += red[w * 32 + tid];                        \
        atomicAdd(&ns[(base) + 2 * tid + (odd)], a); }                             \
    __syncthreads();
    RED4(s1_0, 0, 0)
    RED4(s1_1, 0, 1)
    RED4(s2_0, 64, 0)
    RED4(s2_1, 64, 1)
#undef RED4
}

// ---------------- N2 (float2 vectorized): h = softplus(h + bn(agg)) ----------------
__global__ __launch_bounds__(256) void k_N2(const float* __restrict__ g_bn,
                                            const float* __restrict__ b_bn, int layer) {
    __shared__ float sc[64], sh[64];
    int tid = threadIdx.x;
    if (tid < 64) {
        const float* ns = d_nstat + layer * 128;
        float mean = ns[tid] * (1.f / N_NODES);
        float var = ns[64 + tid] * (1.f / N_NODES) - mean * mean;
        float s = g_bn[layer * 64 + tid] * rsqrtf(var + BN_EPS);
        sc[tid] = s;
        sh[tid] = b_bn[layer * 64 + tid] - mean * s;
    }
    __syncthreads();
    int total2 = N_NODES * NF / 2;
    for (int i = blockIdx.x * 256 + tid; i < total2; i += gridDim.x * 256) {
        int f2 = (i & 31) * 2;
        float2 a = *(const float2*)&d_agg[i * 2];
        float2 hv = *(const float2*)&d_h[i * 2];
        float v0 = fsp(hv.x + fmaf(a.x, sc[f2], sh[f2]));
        float v1 = fsp(hv.y + fmaf(a.y, sc[f2 + 1], sh[f2 + 1]));
        *(float2*)&d_h[i * 2] = make_float2(v0, v1);
        *(__half2*)&d_hh[i * 2] = __floats2half2_rn(v0, v1);
    }
}

// ---------------- final: mean pool per graph + MLP head ----------------
__device__ __forceinline__ int lbound(const int* a, int n, int v) {
    int lo = 0, hi = n;
    while (lo < hi) {
        int mid = (lo + hi) >> 1;
        if (a[mid] < v) lo = mid + 1; else hi = mid;
    }
    return lo;
}

__global__ __launch_bounds__(128) void k_final(const int* __restrict__ gids,
                                               const float* __restrict__ Wfc,
                                               const float* __restrict__ bfc,
                                               const float* __restrict__ Wout,
                                               const float* __restrict__ bout,
                                               float* __restrict__ out) {
    int g = blockIdx.x;
    int tid = threadIdx.x;
    __shared__ int bounds[2];
    __shared__ float f1s[64];
    __shared__ float red[128];
    if (tid == 0) {
        bounds[0] = lbound(gids, N_NODES, g);
        bounds[1] = lbound(gids, N_NODES, g + 1);
    }
    __syncthreads();
    int lo = bounds[0], hi = bounds[1];
    int f = tid & 63, half = tid >> 6;
    float s = 0.f;
    for (int n = lo + half; n < hi; n += 2) s += d_h[n * 64 + f];
    red[tid] = s;
    __syncthreads();
    if (tid < 64) {
        float tot = red[tid] + red[tid + 64];
        float cnt = (float)max(hi - lo, 1);
        f1s[tid] = fsp(tot / cnt);
    }
    __syncthreads();
    float acc = bfc[tid];
#pragma unroll
    for (int k = 0; k < 64; k++) acc = fmaf(f1s[k], Wfc[k * FCF + tid], acc);
    float v = fsp(fsp(acc)) * Wout[tid];
    red[tid] = v;
    __syncthreads();
    for (int st = 64; st > 0; st >>= 1) {
        if (tid < st) red[tid] += red[tid + st];
        __syncthreads();
    }
    if (tid == 0) out[g] = red[0] + bout[0];
}

// ---------------- launch ----------------
extern "C" void kernel_launch(void* const* d_in, const int* in_sizes, int n_in,
                              void* d_out, int out_size) {
    const float* atom  = (const float*)d_in[0];
    const float* bond  = (const float*)d_in[1];
    const int*   src   = (const int*)d_in[2];
    const int*   dst   = (const int*)d_in[3];
    const int*   gids  = (const int*)d_in[4];
    const float* W_emb = (const float*)d_in[5];
    const float* b_emb = (const float*)d_in[6];
    const float* Wi    = (const float*)d_in[7];
    // d_in[8] = bi  — cancels inside training-mode BatchNorm
    const float* gi    = (const float*)d_in[9];
    const float* bti   = (const float*)d_in[10];
    const float* Wu    = (const float*)d_in[11];
    // d_in[12] = bu — cancels
    const float* gu    = (const float*)d_in[13];
    const float* btu   = (const float*)d_in[14];
    const float* g_bn  = (const float*)d_in[15];
    const float* b_bn  = (const float*)d_in[16];
    const float* W_fc  = (const float*)d_in[17];
    const float* b_fc  = (const float*)d_in[18];
    const float* W_out = (const float*)d_in[19];
    const float* b_out = (const float*)d_in[20];
    float* out = (float*)d_out;

    const int EB = (N_EDGES + 255) / 256;
    const int NB = (N_NODES + 255) / 256;
    const int SB = (N_NODES + 511) / 512;

    k_wbig<<<54, 1024>>>(Wi, Wu, W_emb);
    k_table<<<NLAYERS * TBLK, 256>>>(Wi, Wu);
    k_convatom<<<(NPAD * 24 + 255) / 256, 256>>>(atom);
    k_count<<<EB, 256>>>(dst);
    k_scan1<<<SB, 512>>>();
    k_scan2<<<1, 128>>>(SB);
    k_scan3<<<SB, 512>>>();
    k_fill<<<EB, 256>>>(dst);
    k_sortg<<<NB, 256>>>(src, bond);

    k_gemm_embh<<<NPAD / 128, 256>>>(b_emb);

    for (int l = 0; l < NLAYERS; l++) {
        k_gemmAB<<<NPAD / 64, 256>>>(l);
        k_stats<<<1184, 256>>>(l);
        k_apply<<<1184, 256>>>(gi, bti, gu, btu, l);
        k_N2<<<2048, 256>>>(g_bn, b_bn, l);
    }

    k_final<<<N_GRAPHS, 128>>>(gids, W_fc, b_fc, W_out, b_out, out);
}

// round 16
// speedup vs baseline: 1.0104x; 1.0104x over previous
#include <cuda_runtime.h>
#include <cuda_fp16.h>
#include <mma.h>
#include <math.h>

using namespace nvcuda;

#define N_NODES 50000
#define NPAD 50048          // 782 * 64
#define N_EDGES 400000
#define N_GRAPHS 512
#define NF 64
#define EF 32
#define AIF 92
#define AIFP 96
#define FCF 128
#define NLAYERS 3
#define TBINS 16384
#define TROWS 16385
#define BN_EPS 1e-5f

// ---------------- static scratch ----------------
__device__ __align__(16) float   d_h[NPAD * NF];
__device__ __align__(16) float   d_agg[NPAD * NF];
__device__ __align__(16) __half2 d_ABp[NPAD * 128];            // packed (i,u): [0..63]=A, [64..127]=B
__device__ __align__(16) __half2 d_tab[NLAYERS * TROWS * 64];  // RBF@W table (nearest bin)
__device__ __align__(16) __half  d_wbigh[NLAYERS * 64 * 256];
__device__ __align__(16) __half  d_atomh[NPAD * AIFP];
__device__ __align__(16) __half  d_wembh[AIFP * NF];
__device__ int   d_counts[N_NODES];
__device__ int   d_rowstart[N_NODES + 1];
__device__ int   d_cursor[N_NODES];
__device__ int   d_bsum[128];
__device__ int   d_boff[128];
__device__ int   d_csr_eid[N_EDGES];
__device__ __align__(8) int2 d_e2[N_EDGES];    // (src, tbin), dst implicit in CSR position
__device__ float d_estat[NLAYERS * 256];
__device__ float d_nstat[NLAYERS * 128];

// ---------------- fast math ----------------
__device__ __forceinline__ float fsig(float x) {
    float t, hx = 0.5f * x;
    asm("tanh.approx.f32 %0, %1;" : "=f"(t) : "f"(hx));
    return fmaf(0.5f, t, 0.5f);
}
__device__ __forceinline__ float fsp(float x) {
    return fmaxf(x, 0.f) + __logf(1.f + __expf(-fabsf(x)));
}

// ---------------- prep: pack fp16 weights (interleaved) + embed weights, zero stat slabs ----
__global__ void k_wbig(const float* __restrict__ Wi, const float* __restrict__ Wu,
                       const float* __restrict__ Wemb) {
    int tid = threadIdx.x;
    int idx = blockIdx.x * blockDim.x + tid;
    if (blockIdx.x == 0) {
        if (tid < NLAYERS * 256) d_estat[tid] = 0.f;
    } else if (blockIdx.x == 1) {
        if (tid < NLAYERS * 128) d_nstat[tid] = 0.f;
    }
    for (int i = idx; i < N_NODES; i += gridDim.x * blockDim.x) d_counts[i] = 0;
    if (idx < NLAYERS * 64 * 256) {
        int l = idx / 16384;
        int r = idx - l * 16384;
        int k = r >> 8;
        int c = r & 255;
        float v;
        if (c < 128) {
            int f = c >> 1;
            int base = (l * 160 + k) * 64 + f;
            v = (c & 1) ? Wu[base] : Wi[base];
        } else {
            int f = (c - 128) >> 1;
            int base = (l * 160 + 64 + k) * 64 + f;
            v = (c & 1) ? Wu[base] : Wi[base];
        }
        d_wbigh[idx] = __float2half(v);
    } else {
        int w = idx - NLAYERS * 64 * 256;
        if (w < AIFP * NF) {
            int k = w >> 6, c = w & 63;
            d_wembh[w] = __float2half(k < AIF ? Wemb[k * 64 + c] : 0.f);
        }
    }
}

// ---------------- table build ----------------
#define TCH 64
#define TBLK 257
__global__ __launch_bounds__(256) void k_table(const float* __restrict__ Wi,
                                               const float* __restrict__ Wu) {
    int b = blockIdx.x;
    int l = b / TBLK;
    int t0 = (b - l * TBLK) * TCH;
    int tid = threadIdx.x;
    __shared__ float ws[2][32 * 64];
    __shared__ float es[TCH * 32];
    for (int idx = tid; idx < 32 * 64; idx += 256) {
        int k = idx >> 6, f = idx & 63;
        ws[0][idx] = Wi[(l * 160 + 128 + k) * 64 + f];
        ws[1][idx] = Wu[(l * 160 + 128 + k) * 64 + f];
    }
    for (int idx = tid; idx < TCH * 32; idx += 256) {
        int tl = idx >> 5, k = idx & 31;
        int t = t0 + tl;
        float d = (float)t * (8.0f / (float)TBINS);
        float ck = (float)k * (8.0f / 31.0f);
        float df = d - ck;
        es[idx] = (t < TROWS) ? __expf(-3.875f * df * df) : 0.f;
    }
    __syncthreads();
    for (int o = tid; o < TCH * 64; o += 256) {
        int tl = o >> 6, f = o & 63;
        int t = t0 + tl;
        if (t >= TROWS) continue;
        float ai = 0.f, au = 0.f;
#pragma unroll
        for (int k = 0; k < 32; k++) {
            float e = es[tl * 32 + k];
            ai = fmaf(e, ws[0][k * 64 + f], ai);
            au = fmaf(e, ws[1][k * 64 + f], au);
        }
        d_tab[(l * TROWS + t) * 64 + f] = __floats2half2_rn(ai, au);
    }
}

// ---------------- fp16 conversion of atom features ----------------
__global__ void k_convatom(const float* __restrict__ atom) {
    int idx = blockIdx.x * blockDim.x + threadIdx.x;
    if (idx >= NPAD * 24) return;
    int row = idx / 24, c4 = idx - row * 24;
    float4 v = make_float4(0.f, 0.f, 0.f, 0.f);
    if (row < N_NODES && c4 < 23) v = *(const float4*)&atom[row * AIF + c4 * 4];
    __half2* o = (__half2*)&d_atomh[row * AIFP + c4 * 4];
    o[0] = __floats2half2_rn(v.x, v.y);
    o[1] = __floats2half2_rn(v.z, v.w);
}

// ---------------- CSR build ----------------
__global__ void k_count(const int* __restrict__ dst) {
    int e = blockIdx.x * blockDim.x + threadIdx.x;
    if (e < N_EDGES) atomicAdd(&d_counts[dst[e]], 1);
}

__global__ void k_scan1() {
    int b = blockIdx.x, tid = threadIdx.x;
    int i = b * 512 + tid;
    int v = (i < N_NODES) ? d_counts[i] : 0;
    __shared__ int s[512];
    s[tid] = v;
    __syncthreads();
    for (int o = 1; o < 512; o <<= 1) {
        int t = (tid >= o) ? s[tid - o] : 0;
        __syncthreads();
        s[tid] += t;
        __syncthreads();
    }
    if (i < N_NODES) d_rowstart[i] = s[tid] - v;
    if (tid == 511) d_bsum[b] = s[511];
}

__global__ void k_scan2(int nblk) {
    int tid = threadIdx.x;
    int v = (tid < nblk) ? d_bsum[tid] : 0;
    __shared__ int s[128];
    s[tid] = v;
    __syncthreads();
    for (int o = 1; o < 128; o <<= 1) {
        int t = (tid >= o) ? s[tid - o] : 0;
        __syncthreads();
        s[tid] += t;
        __syncthreads();
    }
    d_boff[tid] = s[tid] - v;
}

__global__ void k_scan3() {
    int i = blockIdx.x * blockDim.x + threadIdx.x;
    if (i >= N_NODES) return;
    int rs = d_rowstart[i] + d_boff[i >> 9];
    d_rowstart[i] = rs;
    d_cursor[i] = rs;
    if (i == 0) d_rowstart[N_NODES] = N_EDGES;
}

__global__ void k_fill(const int* __restrict__ dst) {
    int e = blockIdx.x * blockDim.x + threadIdx.x;
    if (e >= N_EDGES) return;
    int pos = atomicAdd(&d_cursor[dst[e]], 1);
    d_csr_eid[pos] = e;
}

__global__ void k_sortg(const int* __restrict__ src, const float* __restrict__ bond) {
    int n = blockIdx.x * blockDim.x + threadIdx.x;
    if (n >= N_NODES) return;
    int s = d_rowstart[n], e = d_rowstart[n + 1];
    for (int i = s + 1; i < e; i++) {
        int v = d_csr_eid[i];
        int j = i - 1;
        while (j >= s && d_csr_eid[j] > v) {
            d_csr_eid[j + 1] = d_csr_eid[j];
            j--;
        }
        d_csr_eid[j + 1] = v;
    }
    for (int i = s; i < e; i++) {
        int eid = d_csr_eid[i];
        int ss = src[eid];
        int t = __float2int_rn(bond[eid] * ((float)TBINS / 8.0f));
        d_e2[i] = make_int2(ss, t);
    }
}

// ---------------- embed GEMM via HMMA (writes d_h only) ----------------
__global__ __launch_bounds__(256) void k_gemm_embh(const float* __restrict__ bias) {
    int m0 = blockIdx.x * 128;
    int wid = threadIdx.x >> 5;
    int lane = threadIdx.x & 31;
    int mw = wid & 3;
    int nw = wid >> 2;

    wmma::fragment<wmma::accumulator, 16, 16, 16, float> acc[2][2];
#pragma unroll
    for (int mi = 0; mi < 2; mi++)
#pragma unroll
        for (int nj = 0; nj < 2; nj++) wmma::fill_fragment(acc[mi][nj], 0.f);

#pragma unroll
    for (int kk = 0; kk < 6; kk++) {
        wmma::fragment<wmma::matrix_a, 16, 16, 16, __half, wmma::row_major> af[2];
        wmma::fragment<wmma::matrix_b, 16, 16, 16, __half, wmma::row_major> bf[2];
#pragma unroll
        for (int mi = 0; mi < 2; mi++)
            wmma::load_matrix_sync(af[mi], d_atomh + (m0 + mw * 32 + mi * 16) * AIFP + kk * 16, AIFP);
#pragma unroll
        for (int nj = 0; nj < 2; nj++)
            wmma::load_matrix_sync(bf[nj], d_wembh + (kk * 16) * 64 + nw * 32 + nj * 16, 64);
#pragma unroll
        for (int mi = 0; mi < 2; mi++)
#pragma unroll
            for (int nj = 0; nj < 2; nj++)
                wmma::mma_sync(acc[mi][nj], af[mi], bf[nj], acc[mi][nj]);
    }

    __shared__ float patch[8][256];
    float* p = patch[wid];
#pragma unroll
    for (int mi = 0; mi < 2; mi++)
#pragma unroll
        for (int nj = 0; nj < 2; nj++) {
            wmma::store_matrix_sync(p, acc[mi][nj], 16, wmma::mem_row_major);
            __syncwarp();
            int row0 = m0 + mw * 32 + mi * 16;
            int col0 = nw * 32 + nj * 16;
#pragma unroll
            for (int j = 0; j < 8; j++) {
                int q = lane + 32 * j;
                int r = q >> 4, c = q & 15;
                d_h[(row0 + r) * 64 + col0 + c] = p[r * 16 + c] + bias[col0 + c];
            }
            __syncwarp();
        }
}

// ---------------- layer GEMM via HMMA with fused node-update prologue ----------------
// layer 0: A-tile = half(d_h)            (embed output)
// layer>0: A-tile = softplus(h + bn_{layer-1}(agg)); also writes updated d_h
__global__ __launch_bounds__(256) void k_gemmAB(const float* __restrict__ g_bn,
                                                const float* __restrict__ b_bn,
                                                int layer) {
    __shared__ __half As[64 * 64];      // 8 KB A-tile
    __shared__ float sc[64], sh[64];
    int tid = threadIdx.x;
    int m0 = blockIdx.x * 64;

    if (layer > 0) {
        if (tid < 64) {
            const float* ns = d_nstat + (layer - 1) * 128;
            float mean = ns[tid] * (1.f / N_NODES);
            float var = ns[64 + tid] * (1.f / N_NODES) - mean * mean;
            float s = g_bn[(layer - 1) * 64 + tid] * rsqrtf(var + BN_EPS);
            sc[tid] = s;
            sh[tid] = b_bn[(layer - 1) * 64 + tid] - mean * s;
        }
        __syncthreads();
#pragma unroll
        for (int it = 0; it < 8; it++) {
            int idx = it * 256 + tid;        // 2048 float2 slots
            int r = idx >> 5, c2 = idx & 31;
            int o = (m0 + r) * 64 + c2 * 2;
            float2 hv = *(const float2*)&d_h[o];
            float2 av = *(const float2*)&d_agg[o];
            float v0 = fsp(hv.x + fmaf(av.x, sc[c2 * 2], sh[c2 * 2]));
            float v1 = fsp(hv.y + fmaf(av.y, sc[c2 * 2 + 1], sh[c2 * 2 + 1]));
            *(float2*)&d_h[o] = make_float2(v0, v1);
            *(__half2*)&As[r * 64 + c2 * 2] = __floats2half2_rn(v0, v1);
        }
    } else {
#pragma unroll
        for (int it = 0; it < 8; it++) {
            int idx = it * 256 + tid;
            int r = idx >> 5, c2 = idx & 31;
            float2 hv = *(const float2*)&d_h[(m0 + r) * 64 + c2 * 2];
            *(__half2*)&As[r * 64 + c2 * 2] = __floats2half2_rn(hv.x, hv.y);
        }
    }
    __syncthreads();

    const __half* B = d_wbigh + layer * 64 * 256;
    int wid = tid >> 5;
    int lane = tid & 31;
    int mw = wid & 1;
    int nw = wid >> 1;

    wmma::fragment<wmma::accumulator, 16, 16, 16, float> acc[2][4];
#pragma unroll
    for (int mi = 0; mi < 2; mi++)
#pragma unroll
        for (int nj = 0; nj < 4; nj++) wmma::fill_fragment(acc[mi][nj], 0.f);

#pragma unroll
    for (int kk = 0; kk < 4; kk++) {
        wmma::fragment<wmma::matrix_a, 16, 16, 16, __half, wmma::row_major> af[2];
        wmma::fragment<wmma::matrix_b, 16, 16, 16, __half, wmma::row_major> bf[4];
#pragma unroll
        for (int mi = 0; mi < 2; mi++)
            wmma::load_matrix_sync(af[mi], As + (mw * 32 + mi * 16) * 64 + kk * 16, 64);
#pragma unroll
        for (int nj = 0; nj < 4; nj++)
            wmma::load_matrix_sync(bf[nj], B + (kk * 16) * 256 + nw * 64 + nj * 16, 256);
#pragma unroll
        for (int mi = 0; mi < 2; mi++)
#pragma unroll
            for (int nj = 0; nj < 4; nj++)
                wmma::mma_sync(acc[mi][nj], af[mi], bf[nj], acc[mi][nj]);
    }

    __shared__ float patch[8][256];
    float* p = patch[wid];
#pragma unroll
    for (int mi = 0; mi < 2; mi++)
#pragma unroll
        for (int nj = 0; nj < 4; nj++) {
            wmma::store_matrix_sync(p, acc[mi][nj], 16, wmma::mem_row_major);
            __syncwarp();
            int row0 = m0 + mw * 32 + mi * 16;
            int pairbase = nw * 32 + nj * 8;
#pragma unroll
            for (int j = 0; j < 4; j++) {
                int q = lane * 4 + j;
                int r = q >> 3, pp = q & 7;
                d_ABp[(row0 + r) * 128 + pairbase + pp] =
                    __floats2half2_rn(p[r * 16 + 2 * pp], p[r * 16 + 2 * pp + 1]);
            }
            __syncwarp();
        }
}

// ---------------- stats: node-centric, 8-edge half2-staged batches (R14-proven) ----------------
__global__ __launch_bounds__(256) void k_stats(int layer) {
    int tid = threadIdx.x;
    int wid = tid >> 5, lane = tid & 31;
    int f0 = lane, f1 = lane + 32;
    const __half2* Tb = d_tab + layer * TROWS * 64;
    float s1i0 = 0.f, s2i0 = 0.f, s1u0 = 0.f, s2u0 = 0.f;
    float s1i1 = 0.f, s2i1 = 0.f, s1u1 = 0.f, s2u1 = 0.f;
    for (int n = blockIdx.x * 8 + wid; n < N_NODES; n += gridDim.x * 8) {
        int a0 = d_rowstart[n], a1 = d_rowstart[n + 1];
        float2 b0 = __half22float2(d_ABp[n * 128 + 64 + f0]);
        float2 b1 = __half22float2(d_ABp[n * 128 + 64 + f1]);
        int i = a0;
        for (; i + 8 <= a1; i += 8) {
            int2 e[8];
            __half2 ah0[8], ah1[8], uh0[8], uh1[8];
#pragma unroll
            for (int j = 0; j < 8; j++) e[j] = d_e2[i + j];
#pragma unroll
            for (int j = 0; j < 8; j++) {
                ah0[j] = d_ABp[e[j].x * 128 + f0];
                ah1[j] = d_ABp[e[j].x * 128 + f1];
                uh0[j] = Tb[e[j].y * 64 + f0];
                uh1[j] = Tb[e[j].y * 64 + f1];
            }
#pragma unroll
            for (int j = 0; j < 8; j++) {
                float2 a0v = __half22float2(ah0[j]);
                float2 a1v = __half22float2(ah1[j]);
                float2 u0 = __half22float2(uh0[j]);
                float2 u1 = __half22float2(uh1[j]);
                float pi0 = a0v.x + b0.x + u0.x;
                float pu0 = a0v.y + b0.y + u0.y;
                float pi1 = a1v.x + b1.x + u1.x;
                float pu1 = a1v.y + b1.y + u1.y;
                s1i0 += pi0; s2i0 = fmaf(pi0, pi0, s2i0);
                s1u0 += pu0; s2u0 = fmaf(pu0, pu0, s2u0);
                s1i1 += pi1; s2i1 = fmaf(pi1, pi1, s2i1);
                s1u1 += pu1; s2u1 = fmaf(pu1, pu1, s2u1);
            }
        }
        for (; i < a1; i++) {
            int2 e = d_e2[i];
            float2 a0v = __half22float2(d_ABp[e.x * 128 + f0]);
            float2 a1v = __half22float2(d_ABp[e.x * 128 + f1]);
            float2 u0 = __half22float2(Tb[e.y * 64 + f0]);
            float2 u1 = __half22float2(Tb[e.y * 64 + f1]);
            float pi0 = a0v.x + b0.x + u0.x;
            float pu0 = a0v.y + b0.y + u0.y;
            float pi1 = a1v.x + b1.x + u1.x;
            float pu1 = a1v.y + b1.y + u1.y;
            s1i0 += pi0; s2i0 = fmaf(pi0, pi0, s2i0);
            s1u0 += pu0; s2u0 = fmaf(pu0, pu0, s2u0);
            s1i1 += pi1; s2i1 = fmaf(pi1, pi1, s2i1);
            s1u1 += pu1; s2u1 = fmaf(pu1, pu1, s2u1);
        }
    }
    float* es = d_estat + layer * 256;
    __shared__ float red[256];
#define RED8(val, dstidx)                                                          \
    red[tid] = (val); __syncthreads();                                             \
    if (tid < 32) { float a = 0.f;                                                 \
        for (int w = 0; w < 8; w++) a += red[w * 32 + tid];                        \
        atomicAdd(&es[dstidx], a); }                                               \
    __syncthreads();
    RED8(s1i0, tid)
    RED8(s1i1, 32 + tid)
    RED8(s2i0, 64 + tid)
    RED8(s2i1, 96 + tid)
    RED8(s1u0, 128 + tid)
    RED8(s1u1, 160 + tid)
    RED8(s2u0, 192 + tid)
    RED8(s2u1, 224 + tid)
#undef RED8
}

// ---------------- apply: warp-per-node, 8-edge half2-staged batches, fused edge-BN ----------------
__global__ __launch_bounds__(256) void k_apply(const float* __restrict__ gi,
                                               const float* __restrict__ bti,
                                               const float* __restrict__ gu,
                                               const float* __restrict__ btu,
                                               int layer) {
    __shared__ float sci[64], shi[64], scu[64], shu[64];
    int tid = threadIdx.x;
    if (tid < 128) {
        const float* es = d_estat + layer * 256;
        int c = tid;
        if (c < 64) {
            float mean = es[c] * (1.f / N_EDGES);
            float var = es[64 + c] * (1.f / N_EDGES) - mean * mean;
            float s = gi[layer * 64 + c] * rsqrtf(var + BN_EPS);
            sci[c] = s; shi[c] = bti[layer * 64 + c] - mean * s;
        } else {
            int f = c - 64;
            float mean = es[128 + f] * (1.f / N_EDGES);
            float var = es[192 + f] * (1.f / N_EDGES) - mean * mean;
            float s = gu[layer * 64 + f] * rsqrtf(var + BN_EPS);
            scu[f] = s; shu[f] = btu[layer * 64 + f] - mean * s;
        }
    }
    __syncthreads();
    int wid = tid >> 5, lane = tid & 31;
    int f0 = lane, f1 = lane + 32;
    float ci0 = sci[f0], hi0 = shi[f0], cu0 = scu[f0], hu0 = shu[f0];
    float ci1 = sci[f1], hi1 = shi[f1], cu1 = scu[f1], hu1 = shu[f1];
    const __half2* Tb = d_tab + layer * TROWS * 64;
    float s1_0 = 0.f, s2_0 = 0.f, s1_1 = 0.f, s2_1 = 0.f;
    for (int n = blockIdx.x * 8 + wid; n < N_NODES; n += gridDim.x * 8) {
        int a0 = d_rowstart[n], a1 = d_rowstart[n + 1];
        float2 b0 = __half22float2(d_ABp[n * 128 + 64 + f0]);
        float2 b1 = __half22float2(d_ABp[n * 128 + 64 + f1]);
        float acc0 = 0.f, acc1 = 0.f;
        int i = a0;
        for (; i + 8 <= a1; i += 8) {
            int2 e[8];
            __half2 ah0[8], ah1[8], uh0[8], uh1[8];
#pragma unroll
            for (int j = 0; j < 8; j++) e[j] = d_e2[i + j];
#pragma unroll
            for (int j = 0; j < 8; j++) {
                ah0[j] = d_ABp[e[j].x * 128 + f0];
                ah1[j] = d_ABp[e[j].x * 128 + f1];
                uh0[j] = Tb[e[j].y * 64 + f0];
                uh1[j] = Tb[e[j].y * 64 + f1];
            }
#pragma unroll
            for (int j = 0; j < 8; j++) {
                float2 a0v = __half22float2(ah0[j]);
                float2 a1v = __half22float2(ah1[j]);
                float2 u0 = __half22float2(uh0[j]);
                float2 u1 = __half22float2(uh1[j]);
                acc0 = fmaf(fsig(fmaf(a0v.x + b0.x + u0.x, ci0, hi0)),
                            fsp(fmaf(a0v.y + b0.y + u0.y, cu0, hu0)), acc0);
                acc1 = fmaf(fsig(fmaf(a1v.x + b1.x + u1.x, ci1, hi1)),
                            fsp(fmaf(a1v.y + b1.y + u1.y, cu1, hu1)), acc1);
            }
        }
        for (; i < a1; i++) {
            int2 e = d_e2[i];
            float2 a0v = __half22float2(d_ABp[e.x * 128 + f0]);
            float2 a1v = __half22float2(d_ABp[e.x * 128 + f1]);
            float2 u0 = __half22float2(Tb[e.y * 64 + f0]);
            float2 u1 = __half22float2(Tb[e.y * 64 + f1]);
            acc0 = fmaf(fsig(fmaf(a0v.x + b0.x + u0.x, ci0, hi0)),
                        fsp(fmaf(a0v.y + b0.y + u0.y, cu0, hu0)), acc0);
            acc1 = fmaf(fsig(fmaf(a1v.x + b1.x + u1.x, ci1, hi1)),
                        fsp(fmaf(a1v.y + b1.y + u1.y, cu1, hu1)), acc1);
        }
        d_agg[n * 64 + f0] = acc0;
        d_agg[n * 64 + f1] = acc1;
        s1_0 += acc0; s2_0 = fmaf(acc0, acc0, s2_0);
        s1_1 += acc1; s2_1 = fmaf(acc1, acc1, s2_1);
    }
    float* ns = d_nstat + layer * 128;
    __shared__ float red[256];
#define RED4(val, dstidx)                                                          \
    red[tid] = (val); __syncthreads();                                             \
    if (tid < 32) { float a = 0.f;                                                 \
        for (int w = 0; w < 8; w++) a += red[w * 32 + tid];                        \
        atomicAdd(&ns[dstidx], a); }                                               \
    __syncthreads();
    RED4(s1_0, tid)
    RED4(s1_1, 32 + tid)
    RED4(s2_0, 64 + tid)
    RED4(s2_1, 96 + tid)
#undef RED4
}

// ---------------- final N2 (layer 2 only): h = softplus(h + bn(agg)), fp32 only ----------------
__global__ __launch_bounds__(256) void k_N2(const float* __restrict__ g_bn,
                                            const float* __restrict__ b_bn, int layer) {
    __shared__ float sc[64], sh[64];
    int tid = threadIdx.x;
    if (tid < 64) {
        const float* ns = d_nstat + layer * 128;
        float mean = ns[tid] * (1.f / N_NODES);
        float var = ns[64 + tid] * (1.f / N_NODES) - mean * mean;
        float s = g_bn[layer * 64 + tid] * rsqrtf(var + BN_EPS);
        sc[tid] = s;
        sh[tid] = b_bn[layer * 64 + tid] - mean * s;
    }
    __syncthreads();
    int total2 = N_NODES * NF / 2;
    for (int i = blockIdx.x * 256 + tid; i < total2; i += gridDim.x * 256) {
        int f2 = (i & 31) * 2;
        float2 a = *(const float2*)&d_agg[i * 2];
        float2 hv = *(const float2*)&d_h[i * 2];
        float v0 = fsp(hv.x + fmaf(a.x, sc[f2], sh[f2]));
        float v1 = fsp(hv.y + fmaf(a.y, sc[f2 + 1], sh[f2 + 1]));
        *(float2*)&d_h[i * 2] = make_float2(v0, v1);
    }
}

// ---------------- final: mean pool per graph + MLP head ----------------
__device__ __forceinline__ int lbound(const int* a, int n, int v) {
    int lo = 0, hi = n;
    while (lo < hi) {
        int mid = (lo + hi) >> 1;
        if (a[mid] < v) lo = mid + 1; else hi = mid;
    }
    return lo;
}

__global__ __launch_bounds__(128) void k_final(const int* __restrict__ gids,
                                               const float* __restrict__ Wfc,
                                               const float* __restrict__ bfc,
                                               const float* __restrict__ Wout,
                                               const float* __restrict__ bout,
                                               float* __restrict__ out) {
    int g = blockIdx.x;
    int tid = threadIdx.x;
    __shared__ int bounds[2];
    __shared__ float f1s[64];
    __shared__ float red[128];
    if (tid == 0) {
        bounds[0] = lbound(gids, N_NODES, g);
        bounds[1] = lbound(gids, N_NODES, g + 1);
    }
    __syncthreads();
    int lo = bounds[0], hi = bounds[1];
    int f = tid & 63, half = tid >> 6;
    float s = 0.f;
    for (int n = lo + half; n < hi; n += 2) s += d_h[n * 64 + f];
    red[tid] = s;
    __syncthreads();
    if (tid < 64) {
        float tot = red[tid] + red[tid + 64];
        float cnt = (float)max(hi - lo, 1);
        f1s[tid] = fsp(tot / cnt);
    }
    __syncthreads();
    float acc = bfc[tid];
#pragma unroll
    for (int k = 0; k < 64; k++) acc = fmaf(f1s[k], Wfc[k * FCF + tid], acc);
    float v = fsp(fsp(acc)) * Wout[tid];
    red[tid] = v;
    __syncthreads();
    for (int st = 64; st > 0; st >>= 1) {
        if (tid < st) red[tid] += red[tid + st];
        __syncthreads();
    }
    if (tid == 0) out[g] = red[0] + bout[0];
}

// ---------------- launch ----------------
extern "C" void kernel_launch(void* const* d_in, const int* in_sizes, int n_in,
                              void* d_out, int out_size) {
    const float* atom  = (const float*)d_in[0];
    const float* bond  = (const float*)d_in[1];
    const int*   src   = (const int*)d_in[2];
    const int*   dst   = (const int*)d_in[3];
    const int*   gids  = (const int*)d_in[4];
    const float* W_emb = (const float*)d_in[5];
    const float* b_emb = (const float*)d_in[6];
    const float* Wi    = (const float*)d_in[7];
    // d_in[8] = bi  — cancels inside training-mode BatchNorm
    const float* gi    = (const float*)d_in[9];
    const float* bti   = (const float*)d_in[10];
    const float* Wu    = (const float*)d_in[11];
    // d_in[12] = bu — cancels
    const float* gu    = (const float*)d_in[13];
    const float* btu   = (const float*)d_in[14];
    const float* g_bn  = (const float*)d_in[15];
    const float* b_bn  = (const float*)d_in[16];
    const float* W_fc  = (const float*)d_in[17];
    const float* b_fc  = (const float*)d_in[18];
    const float* W_out = (const float*)d_in[19];
    const float* b_out = (const float*)d_in[20];
    float* out = (float*)d_out;

    const int EB = (N_EDGES + 255) / 256;
    const int NB = (N_NODES + 255) / 256;
    const int SB = (N_NODES + 511) / 512;

    k_wbig<<<54, 1024>>>(Wi, Wu, W_emb);
    k_table<<<NLAYERS * TBLK, 256>>>(Wi, Wu);
    k_convatom<<<(NPAD * 24 + 255) / 256, 256>>>(atom);
    k_count<<<EB, 256>>>(dst);
    k_scan1<<<SB, 512>>>();
    k_scan2<<<1, 128>>>(SB);
    k_scan3<<<SB, 512>>>();
    k_fill<<<EB, 256>>>(dst);
    k_sortg<<<NB, 256>>>(src, bond);

    k_gemm_embh<<<NPAD / 128, 256>>>(b_emb);

    for (int l = 0; l < NLAYERS; l++) {
        k_gemmAB<<<NPAD / 64, 256>>>(g_bn, b_bn, l);   // fuses node-update of layer l-1
        k_stats<<<1184, 256>>>(l);
        k_apply<<<1184, 256>>>(gi, bti, gu, btu, l);
    }
    k_N2<<<2048, 256>>>(g_bn, b_bn, NLAYERS - 1);      // final node update for pooling

    k_final<<<N_GRAPHS, 128>>>(gids, W_fc, b_fc, W_out, b_out, out);
}

// round 17
// speedup vs baseline: 1.0725x; 1.0615x over previous
#include <cuda_runtime.h>
#include <cuda_fp16.h>
#include <mma.h>
#include <math.h>

using namespace nvcuda;

#define N_NODES 50000
#define NPAD 50048          // 782 * 64
#define N_EDGES 400000
#define N_GRAPHS 512
#define NF 64
#define EF 32
#define AIF 92
#define AIFP 96
#define FCF 128
#define NLAYERS 3
#define TBINS 16384
#define TROWS 16385
#define BN_EPS 1e-5f

// ---------------- static scratch ----------------
__device__ __align__(16) float   d_h[NPAD * NF];
__device__ __align__(16) float   d_agg[NPAD * NF];
__device__ __align__(16) __half2 d_ABp[NPAD * 128];            // packed (i,u): [0..63]=A, [64..127]=B
__device__ __align__(16) __half2 d_tab[NLAYERS * TROWS * 64];  // RBF@W table (nearest bin)
__device__ __align__(16) __half  d_wbigh[NLAYERS * 64 * 256];
__device__ __align__(16) __half  d_atomh[NPAD * AIFP];
__device__ __align__(16) __half  d_wembh[AIFP * NF];
__device__ int   d_counts[N_NODES];
__device__ int   d_rowstart[N_NODES + 1];
__device__ int   d_cursor[N_NODES];
__device__ int   d_bsum[128];
__device__ int   d_boff[128];
__device__ int   d_csr_eid[N_EDGES];
__device__ __align__(8) int2 d_e2[N_EDGES];    // (src, tbin), dst implicit in CSR position
__device__ float d_estat[NLAYERS * 256];
__device__ float d_nstat[NLAYERS * 128];

// ---------------- fast math ----------------
__device__ __forceinline__ float fsig(float x) {
    float t, hx = 0.5f * x;
    asm("tanh.approx.f32 %0, %1;" : "=f"(t) : "f"(hx));
    return fmaf(0.5f, t, 0.5f);
}
__device__ __forceinline__ float fsp(float x) {
    return fmaxf(x, 0.f) + __logf(1.f + __expf(-fabsf(x)));
}

// ---------------- prep: pack fp16 weights (interleaved) + embed weights, zero stat slabs ----
__global__ void k_wbig(const float* __restrict__ Wi, const float* __restrict__ Wu,
                       const float* __restrict__ Wemb) {
    int tid = threadIdx.x;
    int idx = blockIdx.x * blockDim.x + tid;
    if (blockIdx.x == 0) {
        if (tid < NLAYERS * 256) d_estat[tid] = 0.f;
    } else if (blockIdx.x == 1) {
        if (tid < NLAYERS * 128) d_nstat[tid] = 0.f;
    }
    for (int i = idx; i < N_NODES; i += gridDim.x * blockDim.x) d_counts[i] = 0;
    if (idx < NLAYERS * 64 * 256) {
        int l = idx / 16384;
        int r = idx - l * 16384;
        int k = r >> 8;
        int c = r & 255;
        float v;
        if (c < 128) {
            int f = c >> 1;
            int base = (l * 160 + k) * 64 + f;
            v = (c & 1) ? Wu[base] : Wi[base];
        } else {
            int f = (c - 128) >> 1;
            int base = (l * 160 + 64 + k) * 64 + f;
            v = (c & 1) ? Wu[base] : Wi[base];
        }
        d_wbigh[idx] = __float2half(v);
    } else {
        int w = idx - NLAYERS * 64 * 256;
        if (w < AIFP * NF) {
            int k = w >> 6, c = w & 63;
            d_wembh[w] = __float2half(k < AIF ? Wemb[k * 64 + c] : 0.f);
        }
    }
}

// ---------------- table build ----------------
#define TCH 64
#define TBLK 257
__global__ __launch_bounds__(256) void k_table(const float* __restrict__ Wi,
                                               const float* __restrict__ Wu) {
    int b = blockIdx.x;
    int l = b / TBLK;
    int t0 = (b - l * TBLK) * TCH;
    int tid = threadIdx.x;
    __shared__ float ws[2][32 * 64];
    __shared__ float es[TCH * 32];
    for (int idx = tid; idx < 32 * 64; idx += 256) {
        int k = idx >> 6, f = idx & 63;
        ws[0][idx] = Wi[(l * 160 + 128 + k) * 64 + f];
        ws[1][idx] = Wu[(l * 160 + 128 + k) * 64 + f];
    }
    for (int idx = tid; idx < TCH * 32; idx += 256) {
        int tl = idx >> 5, k = idx & 31;
        int t = t0 + tl;
        float d = (float)t * (8.0f / (float)TBINS);
        float ck = (float)k * (8.0f / 31.0f);
        float df = d - ck;
        es[idx] = (t < TROWS) ? __expf(-3.875f * df * df) : 0.f;
    }
    __syncthreads();
    for (int o = tid; o < TCH * 64; o += 256) {
        int tl = o >> 6, f = o & 63;
        int t = t0 + tl;
        if (t >= TROWS) continue;
        float ai = 0.f, au = 0.f;
#pragma unroll
        for (int k = 0; k < 32; k++) {
            float e = es[tl * 32 + k];
            ai = fmaf(e, ws[0][k * 64 + f], ai);
            au = fmaf(e, ws[1][k * 64 + f], au);
        }
        d_tab[(l * TROWS + t) * 64 + f] = __floats2half2_rn(ai, au);
    }
}

// ---------------- fp16 conversion of atom features ----------------
__global__ void k_convatom(const float* __restrict__ atom) {
    int idx = blockIdx.x * blockDim.x + threadIdx.x;
    if (idx >= NPAD * 24) return;
    int row = idx / 24, c4 = idx - row * 24;
    float4 v = make_float4(0.f, 0.f, 0.f, 0.f);
    if (row < N_NODES && c4 < 23) v = *(const float4*)&atom[row * AIF + c4 * 4];
    __half2* o = (__half2*)&d_atomh[row * AIFP + c4 * 4];
    o[0] = __floats2half2_rn(v.x, v.y);
    o[1] = __floats2half2_rn(v.z, v.w);
}

// ---------------- CSR build ----------------
__global__ void k_count(const int* __restrict__ dst) {
    int e = blockIdx.x * blockDim.x + threadIdx.x;
    if (e < N_EDGES) atomicAdd(&d_counts[dst[e]], 1);
}

__global__ void k_scan1() {
    int b = blockIdx.x, tid = threadIdx.x;
    int i = b * 512 + tid;
    int v = (i < N_NODES) ? d_counts[i] : 0;
    __shared__ int s[512];
    s[tid] = v;
    __syncthreads();
    for (int o = 1; o < 512; o <<= 1) {
        int t = (tid >= o) ? s[tid - o] : 0;
        __syncthreads();
        s[tid] += t;
        __syncthreads();
    }
    if (i < N_NODES) d_rowstart[i] = s[tid] - v;
    if (tid == 511) d_bsum[b] = s[511];
}

__global__ void k_scan2(int nblk) {
    int tid = threadIdx.x;
    int v = (tid < nblk) ? d_bsum[tid] : 0;
    __shared__ int s[128];
    s[tid] = v;
    __syncthreads();
    for (int o = 1; o < 128; o <<= 1) {
        int t = (tid >= o) ? s[tid - o] : 0;
        __syncthreads();
        s[tid] += t;
        __syncthreads();
    }
    d_boff[tid] = s[tid] - v;
}

__global__ void k_scan3() {
    int i = blockIdx.x * blockDim.x + threadIdx.x;
    if (i >= N_NODES) return;
    int rs = d_rowstart[i] + d_boff[i >> 9];
    d_rowstart[i] = rs;
    d_cursor[i] = rs;
    if (i == 0) d_rowstart[N_NODES] = N_EDGES;
}

__global__ void k_fill(const int* __restrict__ dst) {
    int e = blockIdx.x * blockDim.x + threadIdx.x;
    if (e >= N_EDGES) return;
    int pos = atomicAdd(&d_cursor[dst[e]], 1);
    d_csr_eid[pos] = e;
}

__global__ void k_sortg(const int* __restrict__ src, const float* __restrict__ bond) {
    int n = blockIdx.x * blockDim.x + threadIdx.x;
    if (n >= N_NODES) return;
    int s = d_rowstart[n], e = d_rowstart[n + 1];
    for (int i = s + 1; i < e; i++) {
        int v = d_csr_eid[i];
        int j = i - 1;
        while (j >= s && d_csr_eid[j] > v) {
            d_csr_eid[j + 1] = d_csr_eid[j];
            j--;
        }
        d_csr_eid[j + 1] = v;
    }
    for (int i = s; i < e; i++) {
        int eid = d_csr_eid[i];
        int ss = src[eid];
        int t = __float2int_rn(bond[eid] * ((float)TBINS / 8.0f));
        d_e2[i] = make_int2(ss, t);
    }
}

// ---------------- embed GEMM via HMMA (writes d_h only) ----------------
__global__ __launch_bounds__(256) void k_gemm_embh(const float* __restrict__ bias) {
    int m0 = blockIdx.x * 128;
    int wid = threadIdx.x >> 5;
    int lane = threadIdx.x & 31;
    int mw = wid & 3;
    int nw = wid >> 2;

    wmma::fragment<wmma::accumulator, 16, 16, 16, float> acc[2][2];
#pragma unroll
    for (int mi = 0; mi < 2; mi++)
#pragma unroll
        for (int nj = 0; nj < 2; nj++) wmma::fill_fragment(acc[mi][nj], 0.f);

#pragma unroll
    for (int kk = 0; kk < 6; kk++) {
        wmma::fragment<wmma::matrix_a, 16, 16, 16, __half, wmma::row_major> af[2];
        wmma::fragment<wmma::matrix_b, 16, 16, 16, __half, wmma::row_major> bf[2];
#pragma unroll
        for (int mi = 0; mi < 2; mi++)
            wmma::load_matrix_sync(af[mi], d_atomh + (m0 + mw * 32 + mi * 16) * AIFP + kk * 16, AIFP);
#pragma unroll
        for (int nj = 0; nj < 2; nj++)
            wmma::load_matrix_sync(bf[nj], d_wembh + (kk * 16) * 64 + nw * 32 + nj * 16, 64);
#pragma unroll
        for (int mi = 0; mi < 2; mi++)
#pragma unroll
            for (int nj = 0; nj < 2; nj++)
                wmma::mma_sync(acc[mi][nj], af[mi], bf[nj], acc[mi][nj]);
    }

    __shared__ float patch[8][256];
    float* p = patch[wid];
#pragma unroll
    for (int mi = 0; mi < 2; mi++)
#pragma unroll
        for (int nj = 0; nj < 2; nj++) {
            wmma::store_matrix_sync(p, acc[mi][nj], 16, wmma::mem_row_major);
            __syncwarp();
            int row0 = m0 + mw * 32 + mi * 16;
            int col0 = nw * 32 + nj * 16;
#pragma unroll
            for (int j = 0; j < 8; j++) {
                int q = lane + 32 * j;
                int r = q >> 4, c = q & 15;
                d_h[(row0 + r) * 64 + col0 + c] = p[r * 16 + c] + bias[col0 + c];
            }
            __syncwarp();
        }
}

// ---------------- layer GEMM via HMMA with fused node-update prologue ----------------
__global__ __launch_bounds__(256) void k_gemmAB(const float* __restrict__ g_bn,
                                                const float* __restrict__ b_bn,
                                                int layer) {
    __shared__ __half As[64 * 64];
    __shared__ float sc[64], sh[64];
    int tid = threadIdx.x;
    int m0 = blockIdx.x * 64;

    if (layer > 0) {
        if (tid < 64) {
            const float* ns = d_nstat + (layer - 1) * 128;
            float mean = ns[tid] * (1.f / N_NODES);
            float var = ns[64 + tid] * (1.f / N_NODES) - mean * mean;
            float s = g_bn[(layer - 1) * 64 + tid] * rsqrtf(var + BN_EPS);
            sc[tid] = s;
            sh[tid] = b_bn[(layer - 1) * 64 + tid] - mean * s;
        }
        __syncthreads();
#pragma unroll
        for (int it = 0; it < 8; it++) {
            int idx = it * 256 + tid;
            int r = idx >> 5, c2 = idx & 31;
            int o = (m0 + r) * 64 + c2 * 2;
            float2 hv = *(const float2*)&d_h[o];
            float2 av = *(const float2*)&d_agg[o];
            float v0 = fsp(hv.x + fmaf(av.x, sc[c2 * 2], sh[c2 * 2]));
            float v1 = fsp(hv.y + fmaf(av.y, sc[c2 * 2 + 1], sh[c2 * 2 + 1]));
            *(float2*)&d_h[o] = make_float2(v0, v1);
            *(__half2*)&As[r * 64 + c2 * 2] = __floats2half2_rn(v0, v1);
        }
    } else {
#pragma unroll
        for (int it = 0; it < 8; it++) {
            int idx = it * 256 + tid;
            int r = idx >> 5, c2 = idx & 31;
            float2 hv = *(const float2*)&d_h[(m0 + r) * 64 + c2 * 2];
            *(__half2*)&As[r * 64 + c2 * 2] = __floats2half2_rn(hv.x, hv.y);
        }
    }
    __syncthreads();

    const __half* B = d_wbigh + layer * 64 * 256;
    int wid = tid >> 5;
    int lane = tid & 31;
    int mw = wid & 1;
    int nw = wid >> 1;

    wmma::fragment<wmma::accumulator, 16, 16, 16, float> acc[2][4];
#pragma unroll
    for (int mi = 0; mi < 2; mi++)
#pragma unroll
        for (int nj = 0; nj < 4; nj++) wmma::fill_fragment(acc[mi][nj], 0.f);

#pragma unroll
    for (int kk = 0; kk < 4; kk++) {
        wmma::fragment<wmma::matrix_a, 16, 16, 16, __half, wmma::row_major> af[2];
        wmma::fragment<wmma::matrix_b, 16, 16, 16, __half, wmma::row_major> bf[4];
#pragma unroll
        for (int mi = 0; mi < 2; mi++)
            wmma::load_matrix_sync(af[mi], As + (mw * 32 + mi * 16) * 64 + kk * 16, 64);
#pragma unroll
        for (int nj = 0; nj < 4; nj++)
            wmma::load_matrix_sync(bf[nj], B + (kk * 16) * 256 + nw * 64 + nj * 16, 256);
#pragma unroll
        for (int mi = 0; mi < 2; mi++)
#pragma unroll
            for (int nj = 0; nj < 4; nj++)
                wmma::mma_sync(acc[mi][nj], af[mi], bf[nj], acc[mi][nj]);
    }

    __shared__ float patch[8][256];
    float* p = patch[wid];
#pragma unroll
    for (int mi = 0; mi < 2; mi++)
#pragma unroll
        for (int nj = 0; nj < 4; nj++) {
            wmma::store_matrix_sync(p, acc[mi][nj], 16, wmma::mem_row_major);
            __syncwarp();
            int row0 = m0 + mw * 32 + mi * 16;
            int pairbase = nw * 32 + nj * 8;
#pragma unroll
            for (int j = 0; j < 4; j++) {
                int q = lane * 4 + j;
                int r = q >> 3, pp = q & 7;
                d_ABp[(row0 + r) * 128 + pairbase + pp] =
                    __floats2half2_rn(p[r * 16 + 2 * pp], p[r * 16 + 2 * pp + 1]);
            }
            __syncwarp();
        }
}

// ---------------- stats: node-centric, 4-edge half2-staged, high occupancy ----------------
__global__ __launch_bounds__(256, 5) void k_stats(int layer) {
    int tid = threadIdx.x;
    int wid = tid >> 5, lane = tid & 31;
    int f0 = lane, f1 = lane + 32;
    const __half2* Tb = d_tab + layer * TROWS * 64;
    float s1i0 = 0.f, s2i0 = 0.f, s1u0 = 0.f, s2u0 = 0.f;
    float s1i1 = 0.f, s2i1 = 0.f, s1u1 = 0.f, s2u1 = 0.f;
    for (int n = blockIdx.x * 8 + wid; n < N_NODES; n += gridDim.x * 8) {
        int a0 = d_rowstart[n], a1 = d_rowstart[n + 1];
        float2 b0 = __half22float2(d_ABp[n * 128 + 64 + f0]);
        float2 b1 = __half22float2(d_ABp[n * 128 + 64 + f1]);
        int i = a0;
        for (; i + 4 <= a1; i += 4) {
            int2 e[4];
            __half2 ah0[4], ah1[4], uh0[4], uh1[4];
#pragma unroll
            for (int j = 0; j < 4; j++) e[j] = d_e2[i + j];
#pragma unroll
            for (int j = 0; j < 4; j++) {
                ah0[j] = d_ABp[e[j].x * 128 + f0];
                ah1[j] = d_ABp[e[j].x * 128 + f1];
                uh0[j] = Tb[e[j].y * 64 + f0];
                uh1[j] = Tb[e[j].y * 64 + f1];
            }
#pragma unroll
            for (int j = 0; j < 4; j++) {
                float2 a0v = __half22float2(ah0[j]);
                float2 a1v = __half22float2(ah1[j]);
                float2 u0 = __half22float2(uh0[j]);
                float2 u1 = __half22float2(uh1[j]);
                float pi0 = a0v.x + b0.x + u0.x;
                float pu0 = a0v.y + b0.y + u0.y;
                float pi1 = a1v.x + b1.x + u1.x;
                float pu1 = a1v.y + b1.y + u1.y;
                s1i0 += pi0; s2i0 = fmaf(pi0, pi0, s2i0);
                s1u0 += pu0; s2u0 = fmaf(pu0, pu0, s2u0);
                s1i1 += pi1; s2i1 = fmaf(pi1, pi1, s2i1);
                s1u1 += pu1; s2u1 = fmaf(pu1, pu1, s2u1);
            }
        }
        for (; i < a1; i++) {
            int2 e = d_e2[i];
            float2 a0v = __half22float2(d_ABp[e.x * 128 + f0]);
            float2 a1v = __half22float2(d_ABp[e.x * 128 + f1]);
            float2 u0 = __half22float2(Tb[e.y * 64 + f0]);
            float2 u1 = __half22float2(Tb[e.y * 64 + f1]);
            float pi0 = a0v.x + b0.x + u0.x;
            float pu0 = a0v.y + b0.y + u0.y;
            float pi1 = a1v.x + b1.x + u1.x;
            float pu1 = a1v.y + b1.y + u1.y;
            s1i0 += pi0; s2i0 = fmaf(pi0, pi0, s2i0);
            s1u0 += pu0; s2u0 = fmaf(pu0, pu0, s2u0);
            s1i1 += pi1; s2i1 = fmaf(pi1, pi1, s2i1);
            s1u1 += pu1; s2u1 = fmaf(pu1, pu1, s2u1);
        }
    }
    float* es = d_estat + layer * 256;
    __shared__ float red[256];
#define RED8(val, dstidx)                                                          \
    red[tid] = (val); __syncthreads();                                             \
    if (tid < 32) { float a = 0.f;                                                 \
        for (int w = 0; w < 8; w++) a += red[w * 32 + tid];                        \
        atomicAdd(&es[dstidx], a); }                                               \
    __syncthreads();
    RED8(s1i0, tid)
    RED8(s1i1, 32 + tid)
    RED8(s2i0, 64 + tid)
    RED8(s2i1, 96 + tid)
    RED8(s1u0, 128 + tid)
    RED8(s1u1, 160 + tid)
    RED8(s2u0, 192 + tid)
    RED8(s2u1, 224 + tid)
#undef RED8
}

// ---------------- apply: warp-per-node, 4-edge half2-staged, high occupancy, fused BN ----------------
__global__ __launch_bounds__(256, 5) void k_apply(const float* __restrict__ gi,
                                                  const float* __restrict__ bti,
                                                  const float* __restrict__ gu,
                                                  const float* __restrict__ btu,
                                                  int layer) {
    __shared__ float sci[64], shi[64], scu[64], shu[64];
    int tid = threadIdx.x;
    if (tid < 128) {
        const float* es = d_estat + layer * 256;
        int c = tid;
        if (c < 64) {
            float mean = es[c] * (1.f / N_EDGES);
            float var = es[64 + c] * (1.f / N_EDGES) - mean * mean;
            float s = gi[layer * 64 + c] * rsqrtf(var + BN_EPS);
            sci[c] = s; shi[c] = bti[layer * 64 + c] - mean * s;
        } else {
            int f = c - 64;
            float mean = es[128 + f] * (1.f / N_EDGES);
            float var = es[192 + f] * (1.f / N_EDGES) - mean * mean;
            float s = gu[layer * 64 + f] * rsqrtf(var + BN_EPS);
            scu[f] = s; shu[f] = btu[layer * 64 + f] - mean * s;
        }
    }
    __syncthreads();
    int wid = tid >> 5, lane = tid & 31;
    int f0 = lane, f1 = lane + 32;
    float ci0 = sci[f0], hi0 = shi[f0], cu0 = scu[f0], hu0 = shu[f0];
    float ci1 = sci[f1], hi1 = shi[f1], cu1 = scu[f1], hu1 = shu[f1];
    const __half2* Tb = d_tab + layer * TROWS * 64;
    float s1_0 = 0.f, s2_0 = 0.f, s1_1 = 0.f, s2_1 = 0.f;
    for (int n = blockIdx.x * 8 + wid; n < N_NODES; n += gridDim.x * 8) {
        int a0 = d_rowstart[n], a1 = d_rowstart[n + 1];
        float2 b0 = __half22float2(d_ABp[n * 128 + 64 + f0]);
        float2 b1 = __half22float2(d_ABp[n * 128 + 64 + f1]);
        float acc0 = 0.f, acc1 = 0.f;
        int i = a0;
        for (; i + 4 <= a1; i += 4) {
            int2 e[4];
            __half2 ah0[4], ah1[4], uh0[4], uh1[4];
#pragma unroll
            for (int j = 0; j < 4; j++) e[j] = d_e2[i + j];
#pragma unroll
            for (int j = 0; j < 4; j++) {
                ah0[j] = d_ABp[e[j].x * 128 + f0];
                ah1[j] = d_ABp[e[j].x * 128 + f1];
                uh0[j] = Tb[e[j].y * 64 + f0];
                uh1[j] = Tb[e[j].y * 64 + f1];
            }
#pragma unroll
            for (int j = 0; j < 4; j++) {
                float2 a0v = __half22float2(ah0[j]);
                float2 a1v = __half22float2(ah1[j]);
                float2 u0 = __half22float2(uh0[j]);
                float2 u1 = __half22float2(uh1[j]);
                acc0 = fmaf(fsig(fmaf(a0v.x + b0.x + u0.x, ci0, hi0)),
                            fsp(fmaf(a0v.y + b0.y + u0.y, cu0, hu0)), acc0);
                acc1 = fmaf(fsig(fmaf(a1v.x + b1.x + u1.x, ci1, hi1)),
                            fsp(fmaf(a1v.y + b1.y + u1.y, cu1, hu1)), acc1);
            }
        }
        for (; i < a1; i++) {
            int2 e = d_e2[i];
            float2 a0v = __half22float2(d_ABp[e.x * 128 + f0]);
            float2 a1v = __half22float2(d_ABp[e.x * 128 + f1]);
            float2 u0 = __half22float2(Tb[e.y * 64 + f0]);
            float2 u1 = __half22float2(Tb[e.y * 64 + f1]);
            acc0 = fmaf(fsig(fmaf(a0v.x + b0.x + u0.x, ci0, hi0)),
                        fsp(fmaf(a0v.y + b0.y + u0.y, cu0, hu0)), acc0);
            acc1 = fmaf(fsig(fmaf(a1v.x + b1.x + u1.x, ci1, hi1)),
                        fsp(fmaf(a1v.y + b1.y + u1.y, cu1, hu1)), acc1);
        }
        d_agg[n * 64 + f0] = acc0;
        d_agg[n * 64 + f1] = acc1;
        s1_0 += acc0; s2_0 = fmaf(acc0, acc0, s2_0);
        s1_1 += acc1; s2_1 = fmaf(acc1, acc1, s2_1);
    }
    float* ns = d_nstat + layer * 128;
    __shared__ float red[256];
#define RED4(val, dstidx)                                                          \
    red[tid] = (val); __syncthreads();                                             \
    if (tid < 32) { float a = 0.f;                                                 \
        for (int w = 0; w < 8; w++) a += red[w * 32 + tid];                        \
        atomicAdd(&ns[dstidx], a); }                                               \
    __syncthreads();
    RED4(s1_0, tid)
    RED4(s1_1, 32 + tid)
    RED4(s2_0, 64 + tid)
    RED4(s2_1, 96 + tid)
#undef RED4
}

// ---------------- final N2 (layer 2 only): h = softplus(h + bn(agg)), fp32 only ----------------
__global__ __launch_bounds__(256) void k_N2(const float* __restrict__ g_bn,
                                            const float* __restrict__ b_bn, int layer) {
    __shared__ float sc[64], sh[64];
    int tid = threadIdx.x;
    if (tid < 64) {
        const float* ns = d_nstat + layer * 128;
        float mean = ns[tid] * (1.f / N_NODES);
        float var = ns[64 + tid] * (1.f / N_NODES) - mean * mean;
        float s = g_bn[layer * 64 + tid] * rsqrtf(var + BN_EPS);
        sc[tid] = s;
        sh[tid] = b_bn[layer * 64 + tid] - mean * s;
    }
    __syncthreads();
    int total2 = N_NODES * NF / 2;
    for (int i = blockIdx.x * 256 + tid; i < total2; i += gridDim.x * 256) {
        int f2 = (i & 31) * 2;
        float2 a = *(const float2*)&d_agg[i * 2];
        float2 hv = *(const float2*)&d_h[i * 2];
        float v0 = fsp(hv.x + fmaf(a.x, sc[f2], sh[f2]));
        float v1 = fsp(hv.y + fmaf(a.y, sc[f2 + 1], sh[f2 + 1]));
        *(float2*)&d_h[i * 2] = make_float2(v0, v1);
    }
}

// ---------------- final: mean pool per graph + MLP head ----------------
__device__ __forceinline__ int lbound(const int* a, int n, int v) {
    int lo = 0, hi = n;
    while (lo < hi) {
        int mid = (lo + hi) >> 1;
        if (a[mid] < v) lo = mid + 1; else hi = mid;
    }
    return lo;
}

__global__ __launch_bounds__(128) void k_final(const int* __restrict__ gids,
                                               const float* __restrict__ Wfc,
                                               const float* __restrict__ bfc,
                                               const float* __restrict__ Wout,
                                               const float* __restrict__ bout,
                                               float* __restrict__ out) {
    int g = blockIdx.x;
    int tid = threadIdx.x;
    __shared__ int bounds[2];
    __shared__ float f1s[64];
    __shared__ float red[128];
    if (tid == 0) {
        bounds[0] = lbound(gids, N_NODES, g);
        bounds[1] = lbound(gids, N_NODES, g + 1);
    }
    __syncthreads();
    int lo = bounds[0], hi = bounds[1];
    int f = tid & 63, half = tid >> 6;
    float s = 0.f;
    for (int n = lo + half; n < hi; n += 2) s += d_h[n * 64 + f];
    red[tid] = s;
    __syncthreads();
    if (tid < 64) {
        float tot = red[tid] + red[tid + 64];
        float cnt = (float)max(hi - lo, 1);
        f1s[tid] = fsp(tot / cnt);
    }
    __syncthreads();
    float acc = bfc[tid];
#pragma unroll
    for (int k = 0; k < 64; k++) acc = fmaf(f1s[k], Wfc[k * FCF + tid], acc);
    float v = fsp(fsp(acc)) * Wout[tid];
    red[tid] = v;
    __syncthreads();
    for (int st = 64; st > 0; st >>= 1) {
        if (tid < st) red[tid] += red[tid + st];
        __syncthreads();
    }
    if (tid == 0) out[g] = red[0] + bout[0];
}

// ---------------- launch ----------------
extern "C" void kernel_launch(void* const* d_in, const int* in_sizes, int n_in,
                              void* d_out, int out_size) {
    const float* atom  = (const float*)d_in[0];
    const float* bond  = (const float*)d_in[1];
    const int*   src   = (const int*)d_in[2];
    const int*   dst   = (const int*)d_in[3];
    const int*   gids  = (const int*)d_in[4];
    const float* W_emb = (const float*)d_in[5];
    const float* b_emb = (const float*)d_in[6];
    const float* Wi    = (const float*)d_in[7];
    // d_in[8] = bi  — cancels inside training-mode BatchNorm
    const float* gi    = (const float*)d_in[9];
    const float* bti   = (const float*)d_in[10];
    const float* Wu    = (const float*)d_in[11];
    // d_in[12] = bu — cancels
    const float* gu    = (const float*)d_in[13];
    const float* btu   = (const float*)d_in[14];
    const float* g_bn  = (const float*)d_in[15];
    const float* b_bn  = (const float*)d_in[16];
    const float* W_fc  = (const float*)d_in[17];
    const float* b_fc  = (const float*)d_in[18];
    const float* W_out = (const float*)d_in[19];
    const float* b_out = (const float*)d_in[20];
    float* out = (float*)d_out;

    const int EB = (N_EDGES + 255) / 256;
    const int NB = (N_NODES + 255) / 256;
    const int SB = (N_NODES + 511) / 512;

    k_wbig<<<54, 1024>>>(Wi, Wu, W_emb);
    k_table<<<NLAYERS * TBLK, 256>>>(Wi, Wu);
    k_convatom<<<(NPAD * 24 + 255) / 256, 256>>>(atom);
    k_count<<<EB, 256>>>(dst);
    k_scan1<<<SB, 512>>>();
    k_scan2<<<1, 128>>>(SB);
    k_scan3<<<SB, 512>>>();
    k_fill<<<EB, 256>>>(dst);
    k_sortg<<<NB, 256>>>(src, bond);

    k_gemm_embh<<<NPAD / 128, 256>>>(b_emb);

    for (int l = 0; l < NLAYERS; l++) {
        k_gemmAB<<<NPAD / 64, 256>>>(g_bn, b_bn, l);
        k_stats<<<1184, 256>>>(l);
        k_apply<<<1184, 256>>>(gi, bti, gu, btu, l);
    }
    k_N2<<<2048, 256>>>(g_bn, b_bn, NLAYERS - 1);

    k_final<<<N_GRAPHS, 128>>>(gids, W_fc, b_fc, W_out, b_out, out);
}